// round 6
// baseline (speedup 1.0000x reference)
#include <cuda_runtime.h>
#include <math.h>

#define NB   4
#define LEN  64
#define DM   128
#define DI   256
#define DS   16
#define DTR  8
#define EPSF 1e-5f

// ------------------------- device scratch (no allocs) -------------------------
__device__ __align__(16) float g_h  [NB*LEN*DM];   // block output  [b][t][j]
__device__ __align__(16) float g_res[NB*LEN*DM];   // residual      [b][t][j]
__device__ __align__(16) float g_hn [NB*LEN*DM];   // rmsnormed     [b][t][j]
__device__ __align__(16) float g_xc [NB*DI*LEN];   // pre-conv xc   [b][c][t]
__device__ __align__(16) float g_ucm[NB*DI*LEN];   // u=silu(conv)  [b][c][t]
__device__ __align__(16) float g_utm[NB*LEN*DI];   // u             [b][t][c]
__device__ __align__(16) float g_zs [NB*DI*LEN];   // silu(z)       [b][c][t]
__device__ __align__(16) float g_dt [NB*DI*LEN];   // softplus dt   [b][c][t]
__device__ __align__(16) float g_ys [NB*LEN*DI];   // y*silu(z)     [b][t][c]
__device__ __align__(16) float g_Bm [NB*LEN*DS];   // [b][t][n]
__device__ __align__(16) float g_Cm [NB*LEN*DS];   // [b][t][n]

__device__ __forceinline__ float siluf(float x){ return x / (1.0f + __expf(-x)); }
__device__ __forceinline__ float geluf(float x){ return 0.5f*x*(1.0f + erff(x*0.70710678118654752f)); }
__device__ __forceinline__ float softplusf(float x){ return x > 20.0f ? x : log1pf(expf(x)); }

// ------------------- K0: MLP (gelu) for the 4 live sequences -------------------
// grid (16,4): 4 tokens per block; 128 threads = output channel j
__global__ void __launch_bounds__(128) k_mlp(
    const float* __restrict__ xin, const float* __restrict__ w1,
    const float* __restrict__ b1,  const float* __restrict__ w2,
    const float* __restrict__ b2)
{
    int b = blockIdx.y, t0 = blockIdx.x * 4, j = threadIdx.x;
    __shared__ __align__(16) float xs[4][DM];
    __shared__ __align__(16) float h1[4][DM];
    // mha_in element (b, n=0, t, j) at ((b*64 + 0)*64 + t)*128 + j
    const float* xb = xin + ((size_t)(b*4096 + t0)) * DM;
    #pragma unroll
    for (int tt = 0; tt < 4; tt++) xs[tt][j] = xb[tt*DM + j];
    __syncthreads();

    float a[4];
    {
        float bb = b1[j]; a[0]=a[1]=a[2]=a[3]=bb;
        const float4* wr = (const float4*)(w1 + (size_t)j*DM);
        #pragma unroll
        for (int k = 0; k < DM/4; k++){
            float4 w = wr[k];
            #pragma unroll
            for (int tt = 0; tt < 4; tt++){
                float4 v = ((const float4*)xs[tt])[k];
                a[tt] += w.x*v.x + w.y*v.y + w.z*v.z + w.w*v.w;
            }
        }
    }
    #pragma unroll
    for (int tt = 0; tt < 4; tt++) h1[tt][j] = geluf(a[tt]);
    __syncthreads();
    {
        float bb = b2[j]; a[0]=a[1]=a[2]=a[3]=bb;
        const float4* wr = (const float4*)(w2 + (size_t)j*DM);
        #pragma unroll
        for (int k = 0; k < DM/4; k++){
            float4 w = wr[k];
            #pragma unroll
            for (int tt = 0; tt < 4; tt++){
                float4 v = ((const float4*)h1[tt])[k];
                a[tt] += w.x*v.x + w.y*v.y + w.z*v.z + w.w*v.w;
            }
        }
    }
    #pragma unroll
    for (int tt = 0; tt < 4; tt++) g_h[(b*LEN + t0 + tt)*DM + j] = a[tt];
}

// --------------- K1: residual add + rmsnorm (per token) ---------------
// grid (64,4); 128 threads = channel j
__global__ void __launch_bounds__(128) k_resnorm(int first, const float* __restrict__ bnw)
{
    int t = blockIdx.x, b = blockIdx.y, j = threadIdx.x;
    int idx = (b*LEN + t)*DM + j;
    float r = g_h[idx];
    if (!first) r += g_res[idx];
    g_res[idx] = r;
    float s = r * r;
    #pragma unroll
    for (int o = 16; o > 0; o >>= 1) s += __shfl_xor_sync(0xffffffffu, s, o);
    __shared__ float ws[4];
    if ((j & 31) == 0) ws[j >> 5] = s;
    __syncthreads();
    s = ws[0] + ws[1] + ws[2] + ws[3];
    g_hn[idx] = r * rsqrtf(s * (1.0f/DM) + EPSF) * bnw[j];
}

// --------------- K2: in_proj (xz = hn @ W.T), split xc / silu(z) ---------------
// grid (16,4,2): 4 tokens per block, z chooses channel half; 128 threads, 2 ch each
__global__ void __launch_bounds__(128) k_inproj(const float* __restrict__ W)
{
    int b = blockIdx.y, t0 = blockIdx.x * 4, z = blockIdx.z, j = threadIdx.x;
    __shared__ __align__(16) float xs[4][DM];
    #pragma unroll
    for (int tt = 0; tt < 4; tt++) xs[tt][j] = g_hn[(b*LEN + t0 + tt)*DM + j];
    __syncthreads();
    #pragma unroll
    for (int cc = 0; cc < 2; cc++){
        int c = z*256 + cc*128 + j;            // 0..511
        const float4* wr = (const float4*)(W + (size_t)c*DM);
        float a[4] = {0,0,0,0};
        #pragma unroll
        for (int k = 0; k < DM/4; k++){
            float4 w = wr[k];
            #pragma unroll
            for (int tt = 0; tt < 4; tt++){
                float4 v = ((const float4*)xs[tt])[k];
                a[tt] += w.x*v.x + w.y*v.y + w.z*v.z + w.w*v.w;
            }
        }
        #pragma unroll
        for (int tt = 0; tt < 4; tt++){
            if (c < DI) g_xc[(b*DI + c)*LEN + t0 + tt] = a[tt];
            else        g_zs[(b*DI + (c - DI))*LEN + t0 + tt] = siluf(a[tt]);
        }
    }
}

// --------------- K3: causal depthwise conv (width 4) + bias + silu ---------------
// grid 8 x 128 threads = 1024 (b,c) pairs
__global__ void __launch_bounds__(128) k_conv(const float* __restrict__ cw,
                                              const float* __restrict__ cb)
{
    int gid = blockIdx.x*128 + threadIdx.x;
    int b = gid >> 8, c = gid & 255;
    float w0 = cw[c*4+0], w1 = cw[c*4+1], w2 = cw[c*4+2], w3 = cw[c*4+3];
    float bb = cb[c];
    const float* x  = g_xc  + (b*DI + c)*LEN;
    float*       uc = g_ucm + (b*DI + c)*LEN;
    float xm3 = 0.f, xm2 = 0.f, xm1 = 0.f;
    #pragma unroll 4
    for (int t = 0; t < LEN; t++){
        float x0 = x[t];
        float y  = bb + w0*xm3 + w1*xm2 + w2*xm1 + w3*x0;
        float u  = siluf(y);
        uc[t] = u;
        g_utm[(b*LEN + t)*DI + c] = u;
        xm3 = xm2; xm2 = xm1; xm1 = x0;
    }
}

// --------------- K4: x_proj (40 outs) + dt_proj + softplus ---------------
// grid (16,4): 4 tokens/block; 256 threads
__global__ void __launch_bounds__(256) k_xdt(const float* __restrict__ xpw,
                                             const float* __restrict__ dtw,
                                             const float* __restrict__ dtb)
{
    int b = blockIdx.y, t0 = blockIdx.x * 4, tid = threadIdx.x;
    __shared__ __align__(16) float su[4][DI];
    __shared__ float sx[4][DTR];
    #pragma unroll
    for (int tt = 0; tt < 4; tt++) su[tt][tid] = g_utm[(b*LEN + t0 + tt)*DI + tid];
    __syncthreads();
    if (tid < 160){
        int k = tid % 40, tt = tid / 40;
        const float4* wr = (const float4*)(xpw + (size_t)k*DI);
        const float4* uv = (const float4*)su[tt];
        float a = 0.f;
        #pragma unroll
        for (int q = 0; q < DI/4; q++){
            float4 w = wr[q], v = uv[q];
            a += w.x*v.x + w.y*v.y + w.z*v.z + w.w*v.w;
        }
        int t = t0 + tt;
        if (k < DTR)            sx[tt][k] = a;
        else if (k < DTR + DS)  g_Bm[(b*LEN + t)*DS + (k - DTR)]      = a;
        else                    g_Cm[(b*LEN + t)*DS + (k - DTR - DS)] = a;
    }
    __syncthreads();
    int c = tid;
    float bb = dtb[c];
    float wreg[DTR];
    #pragma unroll
    for (int r = 0; r < DTR; r++) wreg[r] = dtw[c*DTR + r];
    #pragma unroll
    for (int tt = 0; tt < 4; tt++){
        float a = bb;
        #pragma unroll
        for (int r = 0; r < DTR; r++) a += sx[tt][r] * wreg[r];
        g_dt[(b*DI + c)*LEN + t0 + tt] = softplusf(a);
    }
}

// --------------- K5: selective scan. thread = (b,c,n); 16-lane reduction ---------------
// grid 128 x 128 threads = 16384
__global__ void __launch_bounds__(128) k_scan(const float* __restrict__ Alog,
                                              const float* __restrict__ Dsk)
{
    int gid = blockIdx.x*128 + threadIdx.x;
    int n = gid & 15, c = (gid >> 4) & 255, b = gid >> 12;
    float A  = -expf(Alog[c*DS + n]);
    float Dv = Dsk[c];
    const float* dtp = g_dt  + (b*DI + c)*LEN;
    const float* up  = g_ucm + (b*DI + c)*LEN;
    const float* zp  = g_zs  + (b*DI + c)*LEN;
    const float* Bp  = g_Bm  + b*LEN*DS + n;
    const float* Cp  = g_Cm  + b*LEN*DS + n;
    float h = 0.f;
    for (int t = 0; t < LEN; t++){
        float dtv = dtp[t], uv = up[t];
        float dA = __expf(dtv * A);
        h = dA*h + (dtv*uv) * Bp[t*DS];
        float y = h * Cp[t*DS];
        y += __shfl_xor_sync(0xffffffffu, y, 1, 16);
        y += __shfl_xor_sync(0xffffffffu, y, 2, 16);
        y += __shfl_xor_sync(0xffffffffu, y, 4, 16);
        y += __shfl_xor_sync(0xffffffffu, y, 8, 16);
        if (n == 0) g_ys[(b*LEN + t)*DI + c] = (y + uv*Dv) * zp[t];
    }
}

// --------------- K6: out_proj ---------------
// grid (16,4): 4 tokens/block; 128 threads = output j
__global__ void __launch_bounds__(128) k_outproj(const float* __restrict__ W)
{
    int b = blockIdx.y, t0 = blockIdx.x * 4, j = threadIdx.x;
    __shared__ __align__(16) float sy[4][DI];
    #pragma unroll
    for (int tt = 0; tt < 4; tt++){
        sy[tt][j]       = g_ys[(b*LEN + t0 + tt)*DI + j];
        sy[tt][j + 128] = g_ys[(b*LEN + t0 + tt)*DI + j + 128];
    }
    __syncthreads();
    const float4* wr = (const float4*)(W + (size_t)j*DI);
    float a[4] = {0,0,0,0};
    #pragma unroll
    for (int k = 0; k < DI/4; k++){
        float4 w = wr[k];
        #pragma unroll
        for (int tt = 0; tt < 4; tt++){
            float4 v = ((const float4*)sy[tt])[k];
            a[tt] += w.x*v.x + w.y*v.y + w.z*v.z + w.w*v.w;
        }
    }
    #pragma unroll
    for (int tt = 0; tt < 4; tt++) g_h[(b*LEN + t0 + tt)*DM + j] = a[tt];
}

// --------------- K7: final residual + rmsnorm at t=63, mask, write out ---------------
// grid 4 x 128
__global__ void __launch_bounds__(128) k_final(const unsigned char* __restrict__ mask,
                                               const float* __restrict__ nfw,
                                               float* __restrict__ out)
{
    int b = blockIdx.x, j = threadIdx.x;
    __shared__ unsigned sb[4];
    __shared__ float ws[4];
    // key_valid(b): any nonzero in mask row (b, n=0, :). Byte-granular read is exact
    // for byte-packed bool storage and stays in-bounds under any element width.
    unsigned v = 0;
    if (j < 64) v = (mask[b*4096 + j] != 0) ? 1u : 0u;
    unsigned bal = __ballot_sync(0xffffffffu, v != 0u);
    if ((j & 31) == 0) sb[j >> 5] = bal;
    __syncthreads();
    int valid = ((sb[0] | sb[1]) != 0u) ? 1 : 0;

    int idx = (b*LEN + 63)*DM + j;
    float r = g_h[idx] + g_res[idx];
    float s = r * r;
    #pragma unroll
    for (int o = 16; o > 0; o >>= 1) s += __shfl_xor_sync(0xffffffffu, s, o);
    if ((j & 31) == 0) ws[j >> 5] = s;
    __syncthreads();
    s = ws[0] + ws[1] + ws[2] + ws[3];
    float o = r * rsqrtf(s * (1.0f/DM) + EPSF) * nfw[j];
    out[b*DM + j] = valid ? o : 0.0f;
}

// --------------------------------- launch ---------------------------------
extern "C" void kernel_launch(void* const* d_in, const int* in_sizes, int n_in,
                              void* d_out, int out_size)
{
    const float* mha = (const float*)d_in[0];
    const unsigned char* mask = (const unsigned char*)d_in[1];
    const float* w1  = (const float*)d_in[2];
    const float* b1  = (const float*)d_in[3];
    const float* w2  = (const float*)d_in[4];
    const float* b2  = (const float*)d_in[5];
    const float* inw = (const float*)d_in[6];
    const float* cw  = (const float*)d_in[7];
    const float* cb  = (const float*)d_in[8];
    const float* xpw = (const float*)d_in[9];
    const float* dtw = (const float*)d_in[10];
    const float* dtb = (const float*)d_in[11];
    const float* alg = (const float*)d_in[12];
    const float* dsk = (const float*)d_in[13];
    const float* ow  = (const float*)d_in[14];
    const float* bnw = (const float*)d_in[15];
    const float* nfw = (const float*)d_in[16];
    float* out = (float*)d_out;

    k_mlp<<<dim3(16,4), 128>>>(mha, w1, b1, w2, b2);
    for (int i = 0; i < 4; i++){
        k_resnorm<<<dim3(64,4),  128>>>(i == 0 ? 1 : 0, bnw + i*DM);
        k_inproj <<<dim3(16,4,2),128>>>(inw + (size_t)i*2*DI*DM);
        k_conv   <<<8,           128>>>(cw + i*DI*4, cb + i*DI);
        k_xdt    <<<dim3(16,4),  256>>>(xpw + (size_t)i*(DTR+2*DS)*DI,
                                        dtw + i*DI*DTR, dtb + i*DI);
        k_scan   <<<128,         128>>>(alg + i*DI*DS, dsk + i*DI);
        k_outproj<<<dim3(16,4),  128>>>(ow + (size_t)i*DM*DI);
    }
    k_final<<<4, 128>>>(mask, nfw, out);
}

// round 7
// speedup vs baseline: 1.3275x; 1.3275x over previous
#include <cuda_runtime.h>
#include <math.h>

#define NB   4
#define LEN  64
#define DM   128
#define DI   256
#define DS   16
#define DTR  8
#define EPSF 1e-5f
#define NBLK 128
#define NTHR 128

// ------------------------- device scratch (no allocs) -------------------------
__device__ __align__(16) float g_res[NB*LEN*DM];   // residual      [b][t][j]
__device__ __align__(16) float g_hn [NB*LEN*DM];   // rmsnormed     [b][t][j]
__device__ __align__(16) float g_xc [NB*DI*LEN];   // pre-conv xc   [b][c][t]
__device__ __align__(16) float g_ucm[NB*DI*LEN];   // u=silu(conv)  [b][c][t]
__device__ __align__(16) float g_utm[NB*LEN*DI];   // u             [b][t][c]
__device__ __align__(16) float g_zs [NB*DI*LEN];   // silu(z)       [b][c][t]
__device__ __align__(16) float g_dt [NB*DI*LEN];   // softplus dt   [b][c][t]
__device__ __align__(16) float g_ys [NB*LEN*DI];   // y*silu(z)     [b][t][c]
__device__ __align__(16) float g_Bm [NB*LEN*DS];   // [b][t][n]
__device__ __align__(16) float g_Cm [NB*LEN*DS];   // [b][t][n]

__device__ unsigned g_barcnt = 0;
__device__ volatile unsigned g_bargen = 0;

__device__ __forceinline__ float siluf(float x){ return x / (1.0f + __expf(-x)); }
__device__ __forceinline__ float geluf(float x){ return 0.5f*x*(1.0f + erff(x*0.70710678118654752f)); }
__device__ __forceinline__ float softplusf(float x){ return x > 20.0f ? x : log1pf(expf(x)); }

// sense-reversing grid barrier; all NBLK blocks must call.
__device__ __forceinline__ void gbar()
{
    __syncthreads();
    if (threadIdx.x == 0){
        __threadfence();
        unsigned gen = g_bargen;
        if (atomicAdd(&g_barcnt, 1u) == (unsigned)(NBLK - 1)){
            atomicExch(&g_barcnt, 0u);
            __threadfence();
            g_bargen = gen + 1u;
        } else {
            while (g_bargen == gen) { __nanosleep(32); }
        }
    }
    __syncthreads();
}

__global__ void __launch_bounds__(NTHR, 1) mamba_fused(
    const float* __restrict__ mha, const unsigned char* __restrict__ mask,
    const float* __restrict__ w1,  const float* __restrict__ b1,
    const float* __restrict__ w2,  const float* __restrict__ b2,
    const float* __restrict__ inw, const float* __restrict__ cw,
    const float* __restrict__ cb,  const float* __restrict__ xpw,
    const float* __restrict__ dtw, const float* __restrict__ dtb,
    const float* __restrict__ alg, const float* __restrict__ dsk,
    const float* __restrict__ ow,  const float* __restrict__ bnw,
    const float* __restrict__ nfw, float* __restrict__ out)
{
    const int blk = blockIdx.x, tid = threadIdx.x;
    const int wid = tid >> 5, lane = tid & 31;
    __shared__ __align__(16) float sA[4][DI];   // 4 KB
    __shared__ __align__(16) float sB[4][DM];   // 2 KB
    __shared__ float sred[4][4];
    __shared__ float sx[4][DTR];

    // =============== P0: MLP (gelu) + residual init + rmsnorm(layer 0) ===============
    if (blk < 64){
        const int b = blk >> 4, t0 = (blk & 15) * 4, j = tid;
        // mha_in(b, n=0, t, j) at ((b*64 + 0)*64 + t)*128 + j
        const float* xb = mha + ((size_t)(b*4096 + t0)) * DM;
        #pragma unroll
        for (int tt = 0; tt < 4; tt++) sB[tt][j] = xb[tt*DM + j];
        __syncthreads();

        float a[4];
        {   float bb = b1[j]; a[0]=a[1]=a[2]=a[3]=bb;
            const float4* wr = (const float4*)(w1 + (size_t)j*DM);
            #pragma unroll
            for (int k = 0; k < DM/4; k++){
                float4 w = wr[k];
                #pragma unroll
                for (int tt = 0; tt < 4; tt++){
                    float4 v = ((const float4*)sB[tt])[k];
                    a[tt] += w.x*v.x + w.y*v.y + w.z*v.z + w.w*v.w;
                }
            }
        }
        #pragma unroll
        for (int tt = 0; tt < 4; tt++) sA[tt][j] = geluf(a[tt]);
        __syncthreads();
        {   float bb = b2[j]; a[0]=a[1]=a[2]=a[3]=bb;
            const float4* wr = (const float4*)(w2 + (size_t)j*DM);
            #pragma unroll
            for (int k = 0; k < DM/4; k++){
                float4 w = wr[k];
                #pragma unroll
                for (int tt = 0; tt < 4; tt++){
                    float4 v = ((const float4*)sA[tt])[k];
                    a[tt] += w.x*v.x + w.y*v.y + w.z*v.z + w.w*v.w;
                }
            }
        }
        // residual init + rmsnorm with bnw[0]
        #pragma unroll
        for (int tt = 0; tt < 4; tt++){
            g_res[(b*LEN + t0 + tt)*DM + j] = a[tt];
            float s = a[tt]*a[tt];
            #pragma unroll
            for (int o = 16; o > 0; o >>= 1) s += __shfl_xor_sync(0xffffffffu, s, o);
            if (lane == 0) sred[tt][wid] = s;
        }
        __syncthreads();
        #pragma unroll
        for (int tt = 0; tt < 4; tt++){
            float s = sred[tt][0] + sred[tt][1] + sred[tt][2] + sred[tt][3];
            g_hn[(b*LEN + t0 + tt)*DM + j] = a[tt] * rsqrtf(s*(1.0f/DM) + EPSF) * bnw[j];
        }
    }
    gbar();

    // =============== layers ===============
    for (int L = 0; L < 4; L++){
        // ---- P2: in_proj. 128 blocks: tg = blk>>1, half = blk&1 ----
        {
            const int tg = blk >> 1, half = blk & 1;
            const int b = tg >> 4, t0 = (tg & 15)*4, j = tid;
            #pragma unroll
            for (int tt = 0; tt < 4; tt++)
                sB[tt][j] = __ldcg(g_hn + (b*LEN + t0 + tt)*DM + j);
            __syncthreads();
            const float* Wi = inw + (size_t)L*2*DI*DM;
            #pragma unroll
            for (int cc = 0; cc < 2; cc++){
                const int c  = half*256 + cc*128 + j;   // row in W, 0..511
                const int cl = cc*128 + j;              // channel within half
                const float4* wr = (const float4*)(Wi + (size_t)c*DM);
                float a[4] = {0,0,0,0};
                #pragma unroll
                for (int k = 0; k < DM/4; k++){
                    float4 w = wr[k];
                    #pragma unroll
                    for (int tt = 0; tt < 4; tt++){
                        float4 v = ((const float4*)sB[tt])[k];
                        a[tt] += w.x*v.x + w.y*v.y + w.z*v.z + w.w*v.w;
                    }
                }
                if (half == 0){
                    #pragma unroll
                    for (int tt = 0; tt < 4; tt++)
                        g_xc[(b*DI + cl)*LEN + t0 + tt] = a[tt];
                } else {
                    #pragma unroll
                    for (int tt = 0; tt < 4; tt++)
                        g_zs[(b*DI + cl)*LEN + t0 + tt] = siluf(a[tt]);
                }
            }
        }
        gbar();

        // ---- P3: causal conv (width 4) + bias + silu — fully parallel over t ----
        {
            const int gid = blk*NTHR + tid;
            const int pair = gid >> 4, b = pair >> 8, c = pair & 255;
            const int t0 = (gid & 15) * 4;
            const float* cwL = cw + ((size_t)L*DI + c)*4;
            const float cw0 = cwL[0], cw1 = cwL[1], cw2 = cwL[2], cw3 = cwL[3];
            const float bb = cb[L*DI + c];
            const float* x = g_xc + (b*DI + c)*LEN;
            float xv[7];
            #pragma unroll
            for (int k = 0; k < 7; k++){
                int t = t0 - 3 + k;
                xv[k] = (t >= 0) ? __ldcg(x + t) : 0.0f;
            }
            #pragma unroll
            for (int jj = 0; jj < 4; jj++){
                float y = bb + cw0*xv[jj] + cw1*xv[jj+1] + cw2*xv[jj+2] + cw3*xv[jj+3];
                float u = siluf(y);
                g_ucm[(b*DI + c)*LEN + t0 + jj] = u;
                g_utm[(b*LEN + t0 + jj)*DI + c] = u;
            }
        }
        gbar();

        // ---- P4: x_proj (40 outs/token) + dt_proj + softplus. blocks 0..63 ----
        if (blk < 64){
            const int b = blk >> 4, t0 = (blk & 15)*4;
            #pragma unroll
            for (int tt = 0; tt < 4; tt++){
                sA[tt][tid]       = __ldcg(g_utm + (b*LEN + t0 + tt)*DI + tid);
                sA[tt][tid + 128] = __ldcg(g_utm + (b*LEN + t0 + tt)*DI + tid + 128);
            }
            __syncthreads();
            const float* xw = xpw + (size_t)L*(DTR + 2*DS)*DI;
            #pragma unroll
            for (int rep = 0; rep < 2; rep++){
                const int task = tid + rep*128;
                if (task < 160){
                    const int k = task % 40, tt = task / 40;
                    const float4* wr = (const float4*)(xw + (size_t)k*DI);
                    const float4* uv = (const float4*)sA[tt];
                    float a = 0.0f;
                    #pragma unroll
                    for (int q = 0; q < DI/4; q++){
                        float4 w = wr[q], v = uv[q];
                        a += w.x*v.x + w.y*v.y + w.z*v.z + w.w*v.w;
                    }
                    const int t = t0 + tt;
                    if (k < DTR)            sx[tt][k] = a;
                    else if (k < DTR + DS)  g_Bm[(b*LEN + t)*DS + (k - DTR)]      = a;
                    else                    g_Cm[(b*LEN + t)*DS + (k - DTR - DS)] = a;
                }
            }
            __syncthreads();
            const float* dw = dtw + (size_t)L*DI*DTR;
            const float* db = dtb + L*DI;
            #pragma unroll
            for (int cc = 0; cc < 2; cc++){
                const int c = cc*128 + tid;
                float bb = db[c];
                float wreg[DTR];
                #pragma unroll
                for (int r = 0; r < DTR; r++) wreg[r] = dw[c*DTR + r];
                #pragma unroll
                for (int tt = 0; tt < 4; tt++){
                    float a = bb;
                    #pragma unroll
                    for (int r = 0; r < DTR; r++) a += sx[tt][r] * wreg[r];
                    g_dt[(b*DI + c)*LEN + t0 + tt] = softplusf(a);
                }
            }
        }
        gbar();

        // ---- P5: selective scan. thread = (b,c,n); 16-lane reduction ----
        {
            const int gid = blk*NTHR + tid;
            const int n = gid & 15, c = (gid >> 4) & 255, b = gid >> 12;
            const float A  = -expf(alg[(size_t)L*DI*DS + c*DS + n]);
            const float Dv = dsk[L*DI + c];
            const float* dtp = g_dt  + (b*DI + c)*LEN;
            const float* up  = g_ucm + (b*DI + c)*LEN;
            const float* zp  = g_zs  + (b*DI + c)*LEN;
            const float* Bp  = g_Bm  + b*LEN*DS + n;
            const float* Cp  = g_Cm  + b*LEN*DS + n;
            float h = 0.0f;
            for (int t = 0; t < LEN; t++){
                float dtv = __ldcg(dtp + t), uv = __ldcg(up + t);
                float dA = __expf(dtv * A);
                h = dA*h + (dtv*uv) * __ldcg(Bp + t*DS);
                float y = h * __ldcg(Cp + t*DS);
                y += __shfl_xor_sync(0xffffffffu, y, 1, 16);
                y += __shfl_xor_sync(0xffffffffu, y, 2, 16);
                y += __shfl_xor_sync(0xffffffffu, y, 4, 16);
                y += __shfl_xor_sync(0xffffffffu, y, 8, 16);
                if (n == 0)
                    g_ys[(b*LEN + t)*DI + c] = (y + uv*Dv) * __ldcg(zp + t);
            }
        }
        gbar();

        // ---- P6: out_proj + residual add + rmsnorm(next layer). blocks 0..63 ----
        if (blk < 64){
            const int b = blk >> 4, t0 = (blk & 15)*4, j = tid;
            #pragma unroll
            for (int tt = 0; tt < 4; tt++){
                sA[tt][j]       = __ldcg(g_ys + (b*LEN + t0 + tt)*DI + j);
                sA[tt][j + 128] = __ldcg(g_ys + (b*LEN + t0 + tt)*DI + j + 128);
            }
            __syncthreads();
            const float* Wo = ow + (size_t)L*DM*DI;
            const float4* wr = (const float4*)(Wo + (size_t)j*DI);
            float a[4] = {0,0,0,0};
            #pragma unroll
            for (int k = 0; k < DI/4; k++){
                float4 w = wr[k];
                #pragma unroll
                for (int tt = 0; tt < 4; tt++){
                    float4 v = ((const float4*)sA[tt])[k];
                    a[tt] += w.x*v.x + w.y*v.y + w.z*v.z + w.w*v.w;
                }
            }
            float r[4];
            #pragma unroll
            for (int tt = 0; tt < 4; tt++){
                const int idx = (b*LEN + t0 + tt)*DM + j;   // same block wrote g_res
                r[tt] = a[tt] + g_res[idx];
                g_res[idx] = r[tt];
                float s = r[tt]*r[tt];
                #pragma unroll
                for (int o = 16; o > 0; o >>= 1) s += __shfl_xor_sync(0xffffffffu, s, o);
                if (lane == 0) sred[tt][wid] = s;
            }
            __syncthreads();
            if (L < 3){
                const float* bw = bnw + (L + 1)*DM;
                #pragma unroll
                for (int tt = 0; tt < 4; tt++){
                    float s = sred[tt][0] + sred[tt][1] + sred[tt][2] + sred[tt][3];
                    g_hn[(b*LEN + t0 + tt)*DM + j] =
                        r[tt] * rsqrtf(s*(1.0f/DM) + EPSF) * bw[j];
                }
            }
        }
        gbar();
    }

    // =============== P7: final rmsnorm at t=63 + key_valid mask ===============
    if (blk < NB){
        const int b = blk, j = tid;
        // key_valid(b): any nonzero byte in mask row (b, n=0, 0..63)
        unsigned v = 0;
        if (j < 64) v = (mask[b*4096 + j] != 0) ? 1u : 0u;
        unsigned bal = __ballot_sync(0xffffffffu, v != 0u);
        if (lane == 0) sred[0][wid] = __uint_as_float(bal);
        __syncthreads();
        const int valid = ((__float_as_uint(sred[0][0]) |
                            __float_as_uint(sred[0][1])) != 0u) ? 1 : 0;

        float r = __ldcg(g_res + (b*LEN + 63)*DM + j);
        float s = r*r;
        #pragma unroll
        for (int o = 16; o > 0; o >>= 1) s += __shfl_xor_sync(0xffffffffu, s, o);
        if (lane == 0) sred[1][wid] = s;
        __syncthreads();
        s = sred[1][0] + sred[1][1] + sred[1][2] + sred[1][3];
        float o = r * rsqrtf(s*(1.0f/DM) + EPSF) * nfw[j];
        out[b*DM + j] = valid ? o : 0.0f;
    }
}

// --------------------------------- launch ---------------------------------
extern "C" void kernel_launch(void* const* d_in, const int* in_sizes, int n_in,
                              void* d_out, int out_size)
{
    const float* mha = (const float*)d_in[0];
    const unsigned char* mask = (const unsigned char*)d_in[1];
    const float* w1  = (const float*)d_in[2];
    const float* b1  = (const float*)d_in[3];
    const float* w2  = (const float*)d_in[4];
    const float* b2  = (const float*)d_in[5];
    const float* inw = (const float*)d_in[6];
    const float* cw  = (const float*)d_in[7];
    const float* cb  = (const float*)d_in[8];
    const float* xpw = (const float*)d_in[9];
    const float* dtw = (const float*)d_in[10];
    const float* dtb = (const float*)d_in[11];
    const float* alg = (const float*)d_in[12];
    const float* dsk = (const float*)d_in[13];
    const float* ow  = (const float*)d_in[14];
    const float* bnw = (const float*)d_in[15];
    const float* nfw = (const float*)d_in[16];
    float* out = (float*)d_out;

    mamba_fused<<<NBLK, NTHR>>>(mha, mask, w1, b1, w2, b2, inw, cw, cb,
                                xpw, dtw, dtb, alg, dsk, ow, bnw, nfw, out);
}

// round 8
// speedup vs baseline: 1.6544x; 1.2463x over previous
#include <cuda_runtime.h>
#include <math.h>

#define NB   4
#define LEN  64
#define DM   128
#define DI   256
#define DS   16
#define DTR  8
#define EPSF 1e-5f
#define NBLK 64
#define NTHR 128

// ------------------------- device scratch (no allocs) -------------------------
__device__ __align__(16) float g_res[NB*LEN*DM];   // residual      [b][t][j]
__device__ __align__(16) float g_hn [NB*LEN*DM];   // rmsnormed     [b][t][j]
__device__ __align__(16) float g_xc [NB*DI*LEN];   // pre-conv xc   [b][c][t]
__device__ __align__(16) float g_ucm[NB*DI*LEN];   // u=silu(conv)  [b][c][t]
__device__ __align__(16) float g_zs [NB*DI*LEN];   // silu(z)       [b][c][t]
__device__ __align__(16) float g_dt [NB*DI*LEN];   // softplus dt   [b][c][t]
__device__ __align__(16) float g_ys [NB*LEN*DI];   // y*silu(z)     [b][t][c]
__device__ __align__(16) float g_Bm [NB*LEN*DS];   // [b][t][n]
__device__ __align__(16) float g_Cm [NB*LEN*DS];   // [b][t][n]

__device__ volatile unsigned g_arrive[NBLK];
__device__ volatile unsigned g_relgen;

__device__ __forceinline__ float siluf(float x){ return x / (1.0f + __expf(-x)); }
__device__ __forceinline__ float geluf(float x){ return 0.5f*x*(1.0f + erff(x*0.70710678118654752f)); }
__device__ __forceinline__ float softplusf(float x){ return x > 20.0f ? x : log1pf(expf(x)); }

// flag-array grid barrier, monotonic epoch (carries across graph replays).
__device__ __forceinline__ void gbar(unsigned target)
{
    __threadfence();          // release: this thread's prior writes -> L2
    __syncthreads();          // all block threads released
    if (blockIdx.x == 0){
        if (threadIdx.x > 0 && threadIdx.x < NBLK){
            while ((int)(g_arrive[threadIdx.x] - target) < 0) {}
        }
        __syncthreads();
        if (threadIdx.x == 0) g_relgen = target;
    } else {
        if (threadIdx.x == 0){
            g_arrive[blockIdx.x] = target;
            while ((int)(g_relgen - target) < 0) {}
        }
    }
    __syncthreads();
}

__global__ void __launch_bounds__(NTHR) mamba_fused(
    const float* __restrict__ mha, const unsigned char* __restrict__ mask,
    const float* __restrict__ w1,  const float* __restrict__ b1,
    const float* __restrict__ w2,  const float* __restrict__ b2,
    const float* __restrict__ inw, const float* __restrict__ cw,
    const float* __restrict__ cb,  const float* __restrict__ xpw,
    const float* __restrict__ dtw, const float* __restrict__ dtb,
    const float* __restrict__ alg, const float* __restrict__ dsk,
    const float* __restrict__ ow,  const float* __restrict__ bnw,
    const float* __restrict__ nfw, float* __restrict__ out)
{
    const int blk = blockIdx.x, tid = threadIdx.x;
    const int wid = tid >> 5, lane = tid & 31;
    __shared__ __align__(16) float sBuf[2048];   // 8 KB general staging
    __shared__ float sRed[16];
    __shared__ float sDt[32];
    unsigned ep = g_relgen;                      // stable base (no writers in flight)

    // =============== P0: MLP (gelu) + residual init + rmsnorm(layer 0) ===============
    {
        const int b = blk >> 4, t0 = (blk & 15) * 4, j = tid;
        float* xs = sBuf;            // [4][128]
        float* h1 = sBuf + 512;      // [4][128]
        const float* xb = mha + ((size_t)(b*4096 + t0)) * DM;  // (b, n=0, t, :)
        #pragma unroll
        for (int tt = 0; tt < 4; tt++) xs[tt*DM + j] = xb[tt*DM + j];
        __syncthreads();

        float a[4];
        {   float bb = b1[j]; a[0]=a[1]=a[2]=a[3]=bb;
            const float4* wr = (const float4*)(w1 + (size_t)j*DM);
            #pragma unroll 8
            for (int k = 0; k < DM/4; k++){
                float4 w = wr[k];
                #pragma unroll
                for (int tt = 0; tt < 4; tt++){
                    float4 v = ((const float4*)(xs + tt*DM))[k];
                    a[tt] += w.x*v.x + w.y*v.y + w.z*v.z + w.w*v.w;
                }
            }
        }
        #pragma unroll
        for (int tt = 0; tt < 4; tt++) h1[tt*DM + j] = geluf(a[tt]);
        __syncthreads();
        {   float bb = b2[j]; a[0]=a[1]=a[2]=a[3]=bb;
            const float4* wr = (const float4*)(w2 + (size_t)j*DM);
            #pragma unroll 8
            for (int k = 0; k < DM/4; k++){
                float4 w = wr[k];
                #pragma unroll
                for (int tt = 0; tt < 4; tt++){
                    float4 v = ((const float4*)(h1 + tt*DM))[k];
                    a[tt] += w.x*v.x + w.y*v.y + w.z*v.z + w.w*v.w;
                }
            }
        }
        #pragma unroll
        for (int tt = 0; tt < 4; tt++){
            g_res[(b*LEN + t0 + tt)*DM + j] = a[tt];
            float s = a[tt]*a[tt];
            #pragma unroll
            for (int o = 16; o > 0; o >>= 1) s += __shfl_xor_sync(0xffffffffu, s, o);
            if (lane == 0) sRed[tt*4 + wid] = s;
        }
        __syncthreads();
        #pragma unroll
        for (int tt = 0; tt < 4; tt++){
            float s = sRed[tt*4+0] + sRed[tt*4+1] + sRed[tt*4+2] + sRed[tt*4+3];
            g_hn[(b*LEN + t0 + tt)*DM + j] = a[tt] * rsqrtf(s*(1.0f/DM) + EPSF) * bnw[j];
        }
    }
    gbar(++ep);

    // =============== layers ===============
    for (int L = 0; L < 4; L++){
        // ---- A: in_proj -> xc (c-major), silu(z) (c-major). block = token group ----
        {
            const int b = blk >> 4, t0 = (blk & 15)*4, j = tid;
            float* xs = sBuf;        // [4][128]
            #pragma unroll
            for (int tt = 0; tt < 4; tt++)
                xs[tt*DM + j] = g_hn[(b*LEN + t0 + tt)*DM + j];   // own-block data
            __syncthreads();
            const float* Wi = inw + (size_t)L*2*DI*DM;
            #pragma unroll
            for (int rr = 0; rr < 4; rr++){
                const int r = rr*128 + j;           // 0..511
                const float4* wr = (const float4*)(Wi + (size_t)r*DM);
                float a[4] = {0,0,0,0};
                #pragma unroll 8
                for (int k = 0; k < DM/4; k++){
                    float4 w = wr[k];
                    #pragma unroll
                    for (int tt = 0; tt < 4; tt++){
                        float4 v = ((const float4*)(xs + tt*DM))[k];
                        a[tt] += w.x*v.x + w.y*v.y + w.z*v.z + w.w*v.w;
                    }
                }
                if (r < DI){
                    #pragma unroll
                    for (int tt = 0; tt < 4; tt++)
                        g_xc[(b*DI + r)*LEN + t0 + tt] = a[tt];
                } else {
                    const int c = r - DI;
                    #pragma unroll
                    for (int tt = 0; tt < 4; tt++)
                        g_zs[(b*DI + c)*LEN + t0 + tt] = siluf(a[tt]);
                }
            }
            __syncthreads();
        }
        gbar(++ep);

        // ---- B: conv(width4)+silu + x_proj + dt_proj. block = token group ----
        {
            const int b = blk >> 4, t0 = (blk & 15)*4;
            float* su = sBuf;        // [4][256]
            // conv: 2 channels per thread, each computes its 4 tokens
            #pragma unroll
            for (int cc = 0; cc < 2; cc++){
                const int c = tid + cc*128;
                const float* cwL = cw + ((size_t)L*DI + c)*4;
                const float cw0 = cwL[0], cw1 = cwL[1], cw2 = cwL[2], cw3 = cwL[3];
                const float bb = cb[L*DI + c];
                const float* x = g_xc + (b*DI + c)*LEN;
                float xv[7];
                #pragma unroll
                for (int k = 0; k < 7; k++){
                    int t = t0 - 3 + k;
                    xv[k] = (t >= 0) ? __ldcg(x + t) : 0.0f;
                }
                float u4[4];
                #pragma unroll
                for (int jj = 0; jj < 4; jj++){
                    float y = bb + cw0*xv[jj] + cw1*xv[jj+1] + cw2*xv[jj+2] + cw3*xv[jj+3];
                    u4[jj] = siluf(y);
                    su[jj*256 + c] = u4[jj];
                }
                *(float4*)(g_ucm + (b*DI + c)*LEN + t0) =
                    make_float4(u4[0], u4[1], u4[2], u4[3]);
            }
            __syncthreads();
            // x_proj: 40 outs x 4 tokens = 160 tasks
            const float* xw = xpw + (size_t)L*(DTR + 2*DS)*DI;
            #pragma unroll
            for (int rep = 0; rep < 2; rep++){
                const int task = tid + rep*128;
                if (task < 160){
                    const int k = task % 40, tt = task / 40;
                    const float4* wr = (const float4*)(xw + (size_t)k*DI);
                    const float4* uv = (const float4*)(su + tt*256);
                    float a = 0.0f;
                    #pragma unroll 8
                    for (int q = 0; q < DI/4; q++){
                        float4 w = wr[q], v = uv[q];
                        a += w.x*v.x + w.y*v.y + w.z*v.z + w.w*v.w;
                    }
                    const int t = t0 + tt;
                    if (k < DTR)            sDt[tt*DTR + k] = a;
                    else if (k < DTR + DS)  g_Bm[(b*LEN + t)*DS + (k - DTR)]      = a;
                    else                    g_Cm[(b*LEN + t)*DS + (k - DTR - DS)] = a;
                }
            }
            __syncthreads();
            // dt_proj + softplus: 2 channels per thread
            const float* dw = dtw + (size_t)L*DI*DTR;
            const float* db = dtb + L*DI;
            #pragma unroll
            for (int cc = 0; cc < 2; cc++){
                const int c = tid + cc*128;
                float bb = db[c];
                float wreg[DTR];
                #pragma unroll
                for (int r = 0; r < DTR; r++) wreg[r] = dw[c*DTR + r];
                float d4[4];
                #pragma unroll
                for (int tt = 0; tt < 4; tt++){
                    float a = bb;
                    #pragma unroll
                    for (int r = 0; r < DTR; r++) a += sDt[tt*DTR + r] * wreg[r];
                    d4[tt] = softplusf(a);
                }
                *(float4*)(g_dt + (b*DI + c)*LEN + t0) =
                    make_float4(d4[0], d4[1], d4[2], d4[3]);
            }
            __syncthreads();
        }
        gbar(++ep);

        // ---- C: selective scan. thread = (b, c, half): h[8] in registers ----
        if (blk < 16){
            const int b = blk >> 2, c0 = (blk & 3)*64;
            const int cl = tid >> 1, half = tid & 1, c = c0 + cl;
            float* sBt = sBuf;            // [64][16]
            float* sCt = sBuf + 1024;     // [64][16]
            for (int q = tid; q < 256; q += NTHR){
                ((float4*)sBt)[q] = __ldcg((const float4*)(g_Bm + b*LEN*DS) + q);
                ((float4*)sCt)[q] = __ldcg((const float4*)(g_Cm + b*LEN*DS) + q);
            }
            __syncthreads();
            float A8[8];
            const float* ap = alg + ((size_t)L*DI + c)*DS + half*8;
            #pragma unroll
            for (int n = 0; n < 8; n++) A8[n] = -expf(ap[n]);
            const float Dv = dsk[L*DI + c];
            const float4* dtp = (const float4*)(g_dt  + (b*DI + c)*LEN);
            const float4* up  = (const float4*)(g_ucm + (b*DI + c)*LEN);
            const float4* zp  = (const float4*)(g_zs  + (b*DI + c)*LEN);
            float h[8];
            #pragma unroll
            for (int n = 0; n < 8; n++) h[n] = 0.0f;
            for (int tq = 0; tq < LEN/4; tq++){
                float4 dt4 = __ldcg(dtp + tq);
                float4 u4  = __ldcg(up  + tq);
                float4 z4  = __ldcg(zp  + tq);
                const float* dta = (const float*)&dt4;
                const float* ua  = (const float*)&u4;
                const float* za  = (const float*)&z4;
                #pragma unroll
                for (int s = 0; s < 4; s++){
                    const int t = tq*4 + s;
                    const float dtv = dta[s], uv = ua[s], zv = za[s];
                    const float dtu = dtv * uv;
                    float4 bv0 = ((const float4*)(sBt + t*DS + half*8))[0];
                    float4 bv1 = ((const float4*)(sBt + t*DS + half*8))[1];
                    float4 cv0 = ((const float4*)(sCt + t*DS + half*8))[0];
                    float4 cv1 = ((const float4*)(sCt + t*DS + half*8))[1];
                    const float* bvv = (const float*)&bv0;   // bv0,bv1 contiguous? no —
                    float bb[8] = {bv0.x,bv0.y,bv0.z,bv0.w,bv1.x,bv1.y,bv1.z,bv1.w};
                    float cc[8] = {cv0.x,cv0.y,cv0.z,cv0.w,cv1.x,cv1.y,cv1.z,cv1.w};
                    (void)bvv;
                    float y = 0.0f;
                    #pragma unroll
                    for (int n = 0; n < 8; n++){
                        float dA = __expf(dtv * A8[n]);
                        h[n] = h[n]*dA + dtu*bb[n];
                        y += h[n]*cc[n];
                    }
                    y += __shfl_xor_sync(0xffffffffu, y, 1);
                    if (half == 0)
                        g_ys[(b*LEN + t)*DI + c] = (y + uv*Dv) * zv;
                }
            }
            __syncthreads();
        }
        gbar(++ep);

        // ---- D: out_proj + residual + rmsnorm(next). block = token group ----
        {
            const int b = blk >> 4, t0 = (blk & 15)*4, j = tid;
            float* sy = sBuf;        // [4][256]
            #pragma unroll
            for (int tt = 0; tt < 4; tt++){
                sy[tt*DI + j]       = __ldcg(g_ys + (b*LEN + t0 + tt)*DI + j);
                sy[tt*DI + j + 128] = __ldcg(g_ys + (b*LEN + t0 + tt)*DI + j + 128);
            }
            __syncthreads();
            const float* Wo = ow + (size_t)L*DM*DI;
            const float4* wr = (const float4*)(Wo + (size_t)j*DI);
            float a[4] = {0,0,0,0};
            #pragma unroll 8
            for (int k = 0; k < DI/4; k++){
                float4 w = wr[k];
                #pragma unroll
                for (int tt = 0; tt < 4; tt++){
                    float4 v = ((const float4*)(sy + tt*DI))[k];
                    a[tt] += w.x*v.x + w.y*v.y + w.z*v.z + w.w*v.w;
                }
            }
            float r[4];
            #pragma unroll
            for (int tt = 0; tt < 4; tt++){
                const int idx = (b*LEN + t0 + tt)*DM + j;    // own-block residual
                r[tt] = a[tt] + g_res[idx];
                g_res[idx] = r[tt];
                float s = r[tt]*r[tt];
                #pragma unroll
                for (int o = 16; o > 0; o >>= 1) s += __shfl_xor_sync(0xffffffffu, s, o);
                if (lane == 0) sRed[tt*4 + wid] = s;
            }
            __syncthreads();
            if (L < 3){
                const float* bw = bnw + (L + 1)*DM;
                #pragma unroll
                for (int tt = 0; tt < 4; tt++){
                    float s = sRed[tt*4+0] + sRed[tt*4+1] + sRed[tt*4+2] + sRed[tt*4+3];
                    g_hn[(b*LEN + t0 + tt)*DM + j] =
                        r[tt] * rsqrtf(s*(1.0f/DM) + EPSF) * bw[j];
                }
            }
            __syncthreads();
        }
        gbar(++ep);
    }

    // =============== final rmsnorm at t=63 + key_valid mask ===============
    if (blk < NB){
        const int b = blk, j = tid;
        unsigned v = 0;
        if (j < 64) v = (mask[b*4096 + j] != 0) ? 1u : 0u;   // row (b, n=0, :)
        unsigned bal = __ballot_sync(0xffffffffu, v != 0u);
        if (lane == 0) sRed[wid] = __uint_as_float(bal);
        __syncthreads();
        const int valid = ((__float_as_uint(sRed[0]) | __float_as_uint(sRed[1])) != 0u) ? 1 : 0;

        float r = g_res[(b*LEN + 63)*DM + j];                // own-block data
        float s = r*r;
        #pragma unroll
        for (int o = 16; o > 0; o >>= 1) s += __shfl_xor_sync(0xffffffffu, s, o);
        if (lane == 0) sRed[8 + wid] = s;
        __syncthreads();
        s = sRed[8] + sRed[9] + sRed[10] + sRed[11];
        float o = r * rsqrtf(s*(1.0f/DM) + EPSF) * nfw[j];
        out[b*DM + j] = valid ? o : 0.0f;
    }
}

// --------------------------------- launch ---------------------------------
extern "C" void kernel_launch(void* const* d_in, const int* in_sizes, int n_in,
                              void* d_out, int out_size)
{
    const float* mha = (const float*)d_in[0];
    const unsigned char* mask = (const unsigned char*)d_in[1];
    const float* w1  = (const float*)d_in[2];
    const float* b1  = (const float*)d_in[3];
    const float* w2  = (const float*)d_in[4];
    const float* b2  = (const float*)d_in[5];
    const float* inw = (const float*)d_in[6];
    const float* cw  = (const float*)d_in[7];
    const float* cb  = (const float*)d_in[8];
    const float* xpw = (const float*)d_in[9];
    const float* dtw = (const float*)d_in[10];
    const float* dtb = (const float*)d_in[11];
    const float* alg = (const float*)d_in[12];
    const float* dsk = (const float*)d_in[13];
    const float* ow  = (const float*)d_in[14];
    const float* bnw = (const float*)d_in[15];
    const float* nfw = (const float*)d_in[16];
    float* out = (float*)d_out;

    mamba_fused<<<NBLK, NTHR>>>(mha, mask, w1, b1, w2, b2, inw, cw, cb,
                                xpw, dtw, dtb, alg, dsk, ow, bnw, nfw, out);
}

// round 9
// speedup vs baseline: 1.8296x; 1.1059x over previous
#include <cuda_runtime.h>
#include <math.h>

#define NB   4
#define LEN  64
#define DM   128
#define DI   256
#define DS   16
#define DTR  8
#define EPSF 1e-5f
#define NBLK 64
#define NTHR 128

// ------------------------- device scratch (no allocs) -------------------------
__device__ __align__(16) float g_res[NB*LEN*DM];   // residual      [b][t][j]
__device__ __align__(16) float g_hn [NB*LEN*DM];   // rmsnormed     [b][t][j]
__device__ __align__(16) float g_ucm[NB*DI*LEN];   // u=silu(conv)  [b][c][t]
__device__ __align__(16) float g_zs [NB*DI*LEN];   // silu(z)       [b][c][t]
__device__ __align__(16) float g_dt [NB*DI*LEN];   // softplus dt   [b][c][t]
__device__ __align__(16) float g_ys [NB*LEN*DI];   // y*silu(z)     [b][t][c]
__device__ __align__(16) float g_Bm [NB*LEN*DS];   // [b][t][n]
__device__ __align__(16) float g_Cm [NB*LEN*DS];   // [b][t][n]

__device__ unsigned g_barcnt = 0;   // monotonic arrivals
__device__ unsigned g_relgen = 0;   // monotonic release generation

__device__ __forceinline__ float siluf(float x){ return x / (1.0f + __expf(-x)); }
__device__ __forceinline__ float geluf(float x){ return 0.5f*x*(1.0f + erff(x*0.70710678118654752f)); }
__device__ __forceinline__ float softplusf(float x){ return x > 20.0f ? x : log1pf(expf(x)); }

__device__ __forceinline__ void st_rel(unsigned* p, unsigned v){
    asm volatile("st.global.release.gpu.u32 [%0], %1;" :: "l"(p), "r"(v) : "memory");
}
__device__ __forceinline__ unsigned ld_acq(unsigned* p){
    unsigned v;
    asm volatile("ld.global.acquire.gpu.u32 %0, [%1];" : "=r"(v) : "l"(p) : "memory");
    return v;
}

// monotonic-epoch grid barrier: arrive via atomicAdd, last arriver release-stores
// the generation; others acquire-poll it. ~2 L2 round trips.
__device__ __forceinline__ void gbar(unsigned k)
{
    __syncthreads();
    if (threadIdx.x == 0){
        __threadfence();                               // release block's writes
        unsigned prev = atomicAdd(&g_barcnt, 1u);
        if (prev == k*NBLK - 1u){
            st_rel(&g_relgen, k);
        } else {
            while ((int)(ld_acq(&g_relgen) - k) < 0) {}
        }
    }
    __syncthreads();
}

__global__ void __launch_bounds__(NTHR) mamba_fused(
    const float* __restrict__ mha, const unsigned char* __restrict__ mask,
    const float* __restrict__ w1,  const float* __restrict__ b1,
    const float* __restrict__ w2,  const float* __restrict__ b2,
    const float* __restrict__ inw, const float* __restrict__ cw,
    const float* __restrict__ cb,  const float* __restrict__ xpw,
    const float* __restrict__ dtw, const float* __restrict__ dtb,
    const float* __restrict__ alg, const float* __restrict__ dsk,
    const float* __restrict__ ow,  const float* __restrict__ bnw,
    const float* __restrict__ nfw, float* __restrict__ out)
{
    const int blk = blockIdx.x, tid = threadIdx.x;
    const int wid = tid >> 5, lane = tid & 31;
    __shared__ __align__(16) float smem[5312];   // 21.25 KB staging
    __shared__ float sRed[16];
    unsigned k = ld_acq(&g_relgen);              // stable epoch base

    const int b  = blk >> 4;       // token-group mapping (used by P0/AB/D)
    const int tg = blk & 15;
    const int t0 = tg * 4;

    // =============== P0: MLP (gelu) + residual init + rmsnorm(layer 0) ===============
    {
        const int j = tid;
        float* xs = smem;            // [4][128]
        float* h1 = smem + 512;      // [4][128]
        const float* xb = mha + ((size_t)(b*4096 + t0)) * DM;  // (b, n=0, t, :)
        #pragma unroll
        for (int tt = 0; tt < 4; tt++) xs[tt*DM + j] = xb[tt*DM + j];
        __syncthreads();

        float a[4];
        {   float bb = b1[j]; a[0]=a[1]=a[2]=a[3]=bb;
            const float4* wr = (const float4*)(w1 + (size_t)j*DM);
            #pragma unroll 8
            for (int q = 0; q < DM/4; q++){
                float4 w = wr[q];
                #pragma unroll
                for (int tt = 0; tt < 4; tt++){
                    float4 v = ((const float4*)(xs + tt*DM))[q];
                    a[tt] += w.x*v.x + w.y*v.y + w.z*v.z + w.w*v.w;
                }
            }
        }
        #pragma unroll
        for (int tt = 0; tt < 4; tt++) h1[tt*DM + j] = geluf(a[tt]);
        __syncthreads();
        {   float bb = b2[j]; a[0]=a[1]=a[2]=a[3]=bb;
            const float4* wr = (const float4*)(w2 + (size_t)j*DM);
            #pragma unroll 8
            for (int q = 0; q < DM/4; q++){
                float4 w = wr[q];
                #pragma unroll
                for (int tt = 0; tt < 4; tt++){
                    float4 v = ((const float4*)(h1 + tt*DM))[q];
                    a[tt] += w.x*v.x + w.y*v.y + w.z*v.z + w.w*v.w;
                }
            }
        }
        #pragma unroll
        for (int tt = 0; tt < 4; tt++){
            g_res[(b*LEN + t0 + tt)*DM + j] = a[tt];
            float s = a[tt]*a[tt];
            #pragma unroll
            for (int o = 16; o > 0; o >>= 1) s += __shfl_xor_sync(0xffffffffu, s, o);
            if (lane == 0) sRed[tt*4 + wid] = s;
        }
        __syncthreads();
        #pragma unroll
        for (int tt = 0; tt < 4; tt++){
            float s = sRed[tt*4+0] + sRed[tt*4+1] + sRed[tt*4+2] + sRed[tt*4+3];
            g_hn[(b*LEN + t0 + tt)*DM + j] = a[tt] * rsqrtf(s*(1.0f/DM) + EPSF) * bnw[j];
        }
    }
    gbar(++k);

    // =============== layers ===============
    for (int L = 0; L < 4; L++){
        // ---- AB: in_proj (with 3-token halo) + conv + x_proj + dt_proj ----
        {
            const int j = tid;
            float* xs  = smem;           // [7][128] hn tokens t0-3..t0+3
            float* xcs = smem + 896;     // [7][256] xc
            float* su  = smem + 2688;    // [4][256] u (own tokens)
            float* sDt = smem + 3712;    // [4][8]
            #pragma unroll
            for (int s = 0; s < 7; s++){
                int t = t0 - 3 + s;
                xs[s*128 + j] = (t >= 0) ? __ldcg(g_hn + (b*LEN + t)*DM + j) : 0.0f;
            }
            __syncthreads();
            const float* Wi = inw + (size_t)L*2*DI*DM;
            // xc rows (0..255) for 7 tokens
            #pragma unroll
            for (int rr = 0; rr < 2; rr++){
                const int r = rr*128 + j;
                const float4* wr = (const float4*)(Wi + (size_t)r*DM);
                float a[7] = {0,0,0,0,0,0,0};
                #pragma unroll 4
                for (int q = 0; q < DM/4; q++){
                    float4 w = wr[q];
                    #pragma unroll
                    for (int s = 0; s < 7; s++){
                        float4 v = ((const float4*)(xs + s*128))[q];
                        a[s] += w.x*v.x + w.y*v.y + w.z*v.z + w.w*v.w;
                    }
                }
                #pragma unroll
                for (int s = 0; s < 7; s++) xcs[s*256 + r] = a[s];
            }
            // z rows (256..511) for own 4 tokens
            #pragma unroll
            for (int rr = 0; rr < 2; rr++){
                const int c = rr*128 + j;
                const float4* wr = (const float4*)(Wi + (size_t)(DI + c)*DM);
                float a[4] = {0,0,0,0};
                #pragma unroll 8
                for (int q = 0; q < DM/4; q++){
                    float4 w = wr[q];
                    #pragma unroll
                    for (int s = 0; s < 4; s++){
                        float4 v = ((const float4*)(xs + (3 + s)*128))[q];
                        a[s] += w.x*v.x + w.y*v.y + w.z*v.z + w.w*v.w;
                    }
                }
                *(float4*)(g_zs + (b*DI + c)*LEN + t0) =
                    make_float4(siluf(a[0]), siluf(a[1]), siluf(a[2]), siluf(a[3]));
            }
            __syncthreads();
            // conv (width 4) + silu: 2 channels per thread, tokens t0..t0+3 local
            #pragma unroll
            for (int cc = 0; cc < 2; cc++){
                const int c = tid + cc*128;
                float4 wv = *(const float4*)(cw + ((size_t)L*DI + c)*4);
                const float bb = cb[L*DI + c];
                float xv[7];
                #pragma unroll
                for (int s = 0; s < 7; s++) xv[s] = xcs[s*256 + c];
                float u4[4];
                #pragma unroll
                for (int jj = 0; jj < 4; jj++){
                    float y = bb + wv.x*xv[jj] + wv.y*xv[jj+1] + wv.z*xv[jj+2] + wv.w*xv[jj+3];
                    u4[jj] = siluf(y);
                    su[jj*256 + c] = u4[jj];
                }
                *(float4*)(g_ucm + (b*DI + c)*LEN + t0) =
                    make_float4(u4[0], u4[1], u4[2], u4[3]);
            }
            __syncthreads();
            // x_proj: 40 outs x 4 tokens = 160 tasks over 128 threads
            const float* xw = xpw + (size_t)L*(DTR + 2*DS)*DI;
            #pragma unroll
            for (int rep = 0; rep < 2; rep++){
                const int task = tid + rep*128;
                if (task < 160){
                    const int kk = task % 40, tt = task / 40;
                    const float4* wr = (const float4*)(xw + (size_t)kk*DI);
                    const float4* uv = (const float4*)(su + tt*256);
                    float a = 0.0f;
                    #pragma unroll 8
                    for (int q = 0; q < DI/4; q++){
                        float4 w = wr[q], v = uv[q];
                        a += w.x*v.x + w.y*v.y + w.z*v.z + w.w*v.w;
                    }
                    const int t = t0 + tt;
                    if (kk < DTR)            sDt[tt*DTR + kk] = a;
                    else if (kk < DTR + DS)  g_Bm[(b*LEN + t)*DS + (kk - DTR)]      = a;
                    else                     g_Cm[(b*LEN + t)*DS + (kk - DTR - DS)] = a;
                }
            }
            __syncthreads();
            // dt_proj + softplus: 2 channels per thread
            const float* dw = dtw + (size_t)L*DI*DTR;
            const float* db = dtb + L*DI;
            #pragma unroll
            for (int cc = 0; cc < 2; cc++){
                const int c = tid + cc*128;
                float bb = db[c];
                float wreg[DTR];
                #pragma unroll
                for (int r = 0; r < DTR; r++) wreg[r] = dw[c*DTR + r];
                float d4[4];
                #pragma unroll
                for (int tt = 0; tt < 4; tt++){
                    float a = bb;
                    #pragma unroll
                    for (int r = 0; r < DTR; r++) a += sDt[tt*DTR + r] * wreg[r];
                    d4[tt] = softplusf(a);
                }
                *(float4*)(g_dt + (b*DI + c)*LEN + t0) =
                    make_float4(d4[0], d4[1], d4[2], d4[3]);
            }
            __syncthreads();
        }
        gbar(++k);

        // ---- scan: all 64 blocks; block=(b, 16-channel slice); thread=(c, state-pair) ----
        {
            const int sb = blk >> 4, ch = blk & 15, c0 = ch*16;
            float* sdt = smem;           // [16][68]
            float* suu = smem + 1088;    // [16][68]
            float* szz = smem + 2176;    // [16][68]
            float* sB  = smem + 3264;    // [64][16]
            float* sC  = smem + 4288;    // [64][16]
            for (int q = tid; q < 256; q += NTHR){
                ((float4*)sB)[q] = __ldcg((const float4*)(g_Bm + sb*LEN*DS) + q);
                ((float4*)sC)[q] = __ldcg((const float4*)(g_Cm + sb*LEN*DS) + q);
            }
            for (int it = tid; it < 256; it += NTHR){
                const int cs = it >> 4, q = it & 15;
                *(float4*)(sdt + cs*68 + q*4) =
                    __ldcg((const float4*)(g_dt  + (sb*DI + c0 + cs)*LEN) + q);
                *(float4*)(suu + cs*68 + q*4) =
                    __ldcg((const float4*)(g_ucm + (sb*DI + c0 + cs)*LEN) + q);
                *(float4*)(szz + cs*68 + q*4) =
                    __ldcg((const float4*)(g_zs  + (sb*DI + c0 + cs)*LEN) + q);
            }
            __syncthreads();
            const int cs = tid >> 3, n2 = tid & 7, c = c0 + cs;
            const float* ap = alg + ((size_t)L*DI + c)*DS + 2*n2;
            const float A0 = -expf(ap[0]);
            const float A1 = -expf(ap[1]);
            const float Dv = dsk[L*DI + c];
            const float* pd = sdt + cs*68;
            const float* pu = suu + cs*68;
            const float* pz = szz + cs*68;
            float h0 = 0.0f, h1 = 0.0f;
            #pragma unroll 4
            for (int t = 0; t < LEN; t++){
                const float dtv = pd[t], uv = pu[t];
                const float dtu = dtv * uv;
                float2 Bv = *(const float2*)(sB + t*DS + 2*n2);
                float2 Cv = *(const float2*)(sC + t*DS + 2*n2);
                h0 = h0*__expf(dtv*A0) + dtu*Bv.x;
                h1 = h1*__expf(dtv*A1) + dtu*Bv.y;
                float y = h0*Cv.x + h1*Cv.y;
                y += __shfl_xor_sync(0xffffffffu, y, 1);
                y += __shfl_xor_sync(0xffffffffu, y, 2);
                y += __shfl_xor_sync(0xffffffffu, y, 4);
                if (n2 == 0)
                    g_ys[(sb*LEN + t)*DI + c] = (y + uv*Dv) * pz[t];
            }
            __syncthreads();
        }
        gbar(++k);

        // ---- D: out_proj + residual + rmsnorm(next) [+ fused final on L3] ----
        {
            const int j = tid;
            float* sy = smem;        // [4][256]
            #pragma unroll
            for (int tt = 0; tt < 4; tt++){
                sy[tt*DI + j]       = __ldcg(g_ys + (b*LEN + t0 + tt)*DI + j);
                sy[tt*DI + j + 128] = __ldcg(g_ys + (b*LEN + t0 + tt)*DI + j + 128);
            }
            __syncthreads();
            const float* Wo = ow + (size_t)L*DM*DI;
            const float4* wr = (const float4*)(Wo + (size_t)j*DI);
            float a[4] = {0,0,0,0};
            #pragma unroll 8
            for (int q = 0; q < DI/4; q++){
                float4 w = wr[q];
                #pragma unroll
                for (int tt = 0; tt < 4; tt++){
                    float4 v = ((const float4*)(sy + tt*DI))[q];
                    a[tt] += w.x*v.x + w.y*v.y + w.z*v.z + w.w*v.w;
                }
            }
            float r[4];
            #pragma unroll
            for (int tt = 0; tt < 4; tt++){
                const int idx = (b*LEN + t0 + tt)*DM + j;    // own-block residual
                r[tt] = a[tt] + g_res[idx];
                g_res[idx] = r[tt];
                float s = r[tt]*r[tt];
                #pragma unroll
                for (int o = 16; o > 0; o >>= 1) s += __shfl_xor_sync(0xffffffffu, s, o);
                if (lane == 0) sRed[tt*4 + wid] = s;
            }
            __syncthreads();
            if (L < 3){
                const float* bw = bnw + (L + 1)*DM;
                #pragma unroll
                for (int tt = 0; tt < 4; tt++){
                    float s = sRed[tt*4+0] + sRed[tt*4+1] + sRed[tt*4+2] + sRed[tt*4+3];
                    g_hn[(b*LEN + t0 + tt)*DM + j] =
                        r[tt] * rsqrtf(s*(1.0f/DM) + EPSF) * bw[j];
                }
                __syncthreads();
            } else if (tg == 15){
                // fused final: token 63 is tt=3 of this block; r[3] in registers.
                unsigned v = 0;
                if (j < 64) v = (mask[b*4096 + j] != 0) ? 1u : 0u;  // row (b, n=0, :)
                unsigned bal = __ballot_sync(0xffffffffu, v != 0u);
                if (lane == 0) sRed[8 + wid] = __uint_as_float(bal);
                __syncthreads();
                const int valid = ((__float_as_uint(sRed[8]) |
                                    __float_as_uint(sRed[9])) != 0u) ? 1 : 0;
                float s = sRed[12] + sRed[13] + sRed[14] + sRed[15];   // tt=3 sums
                float o = r[3] * rsqrtf(s*(1.0f/DM) + EPSF) * nfw[j];
                out[b*DM + j] = valid ? o : 0.0f;
            }
        }
        if (L < 3) gbar(++k);
    }
}

// --------------------------------- launch ---------------------------------
extern "C" void kernel_launch(void* const* d_in, const int* in_sizes, int n_in,
                              void* d_out, int out_size)
{
    const float* mha = (const float*)d_in[0];
    const unsigned char* mask = (const unsigned char*)d_in[1];
    const float* w1  = (const float*)d_in[2];
    const float* b1  = (const float*)d_in[3];
    const float* w2  = (const float*)d_in[4];
    const float* b2  = (const float*)d_in[5];
    const float* inw = (const float*)d_in[6];
    const float* cw  = (const float*)d_in[7];
    const float* cb  = (const float*)d_in[8];
    const float* xpw = (const float*)d_in[9];
    const float* dtw = (const float*)d_in[10];
    const float* dtb = (const float*)d_in[11];
    const float* alg = (const float*)d_in[12];
    const float* dsk = (const float*)d_in[13];
    const float* ow  = (const float*)d_in[14];
    const float* bnw = (const float*)d_in[15];
    const float* nfw = (const float*)d_in[16];
    float* out = (float*)d_out;

    mamba_fused<<<NBLK, NTHR>>>(mha, mask, w1, b1, w2, b2, inw, cw, cb,
                                xpw, dtw, dtb, alg, dsk, ow, bnw, nfw, out);
}